// round 3
// baseline (speedup 1.0000x reference)
#include <cuda_runtime.h>
#include <math.h>

// ---------------- problem constants ----------------
static constexpr int cB   = 32;
static constexpr int cS   = 744;
static constexpr int cD   = 512;
static constexpr int cH   = 8;
static constexpr int cHD  = 64;
static constexpr int cL   = 4;
static constexpr int cF   = 2048;           // EXP * D
static constexpr int cBS  = cB * cS;        // 23808 = 186 * 128
static constexpr int cBSH = cBS * cH;       // 190464

// ---------------- scratch (device globals; no allocations allowed) ----------
__device__ float g_h [cBS * cD];
__device__ float g_q [cBS * cD];
__device__ float g_k [cBS * cD];
__device__ float g_v [cBS * cD];
__device__ float g_o [cBS * cD];
__device__ float g_t [cBS * cD];
__device__ float g_n1[cBS * cD];
__device__ float g_t2[cBS * cD];
__device__ float g_f1[(size_t)cBS * cF];

// ---------------- embedding + positional encoding ----------------
__global__ void k_embed(const int* __restrict__ x, const float* __restrict__ emb,
                        const float* __restrict__ pe, float* __restrict__ h)
{
    int i = blockIdx.x * blockDim.x + threadIdx.x;
    const int n4 = cBS * cD / 4;
    if (i >= n4) return;
    int d4 = i & (cD / 4 - 1);
    int bs = i >> 7;               // / (512/4)
    int s  = bs % cS;
    int tok = x[bs];
    float4 e = reinterpret_cast<const float4*>(emb)[tok * (cD / 4) + d4];
    float4 p = reinterpret_cast<const float4*>(pe)[s * (cD / 4) + d4];
    const float sc = 22.62741699796952f;    // sqrt(512)
    float4 r;
    r.x = e.x * sc + p.x; r.y = e.y * sc + p.y;
    r.z = e.z * sc + p.z; r.w = e.w * sc + p.w;
    reinterpret_cast<float4*>(h)[i] = r;
}

// ---------------- fused QKV: [BSH,64] @ W^T for W in {Wq,Wk,Wv} --------------
__global__ __launch_bounds__(256) void k_qkv(
    const float* __restrict__ h,
    const float* __restrict__ Wq, const float* __restrict__ Wk, const float* __restrict__ Wv,
    float* __restrict__ q, float* __restrict__ k, float* __restrict__ v)
{
    __shared__ __align__(16) float xs[64][68];
    __shared__ __align__(16) float ws[64][64];   // transposed: ws[d][e]
    int tid = threadIdx.x;
    int tx = tid & 15, ty = tid >> 4;
    int row0 = blockIdx.x * 64;

    // X tile is a contiguous 64x64 block of h
    #pragma unroll
    for (int u = 0; u < 4; u++) {
        int f = tid + u * 256;
        int r = f >> 4, c4 = f & 15;
        float4 val = reinterpret_cast<const float4*>(h + (size_t)(row0 + r) * 64)[c4];
        *reinterpret_cast<float4*>(&xs[r][c4 * 4]) = val;
    }

    const float* Wm[3] = {Wq, Wk, Wv};
    float*       Om[3] = {q,  k,  v };
    #pragma unroll
    for (int m = 0; m < 3; m++) {
        __syncthreads();
        #pragma unroll
        for (int u = 0; u < 4; u++) {
            int f = tid + u * 256;
            int e = f >> 4, c4 = f & 15;
            float4 w4 = reinterpret_cast<const float4*>(Wm[m] + e * 64)[c4];
            ws[c4 * 4 + 0][e] = w4.x;
            ws[c4 * 4 + 1][e] = w4.y;
            ws[c4 * 4 + 2][e] = w4.z;
            ws[c4 * 4 + 3][e] = w4.w;
        }
        __syncthreads();
        float acc[4][4] = {};
        #pragma unroll
        for (int d = 0; d < 64; d++) {
            float a0 = xs[ty * 4 + 0][d];
            float a1 = xs[ty * 4 + 1][d];
            float a2 = xs[ty * 4 + 2][d];
            float a3 = xs[ty * 4 + 3][d];
            float4 b4 = *reinterpret_cast<const float4*>(&ws[d][tx * 4]);
            acc[0][0] += a0 * b4.x; acc[0][1] += a0 * b4.y; acc[0][2] += a0 * b4.z; acc[0][3] += a0 * b4.w;
            acc[1][0] += a1 * b4.x; acc[1][1] += a1 * b4.y; acc[1][2] += a1 * b4.z; acc[1][3] += a1 * b4.w;
            acc[2][0] += a2 * b4.x; acc[2][1] += a2 * b4.y; acc[2][2] += a2 * b4.z; acc[2][3] += a2 * b4.w;
            acc[3][0] += a3 * b4.x; acc[3][1] += a3 * b4.y; acc[3][2] += a3 * b4.z; acc[3][3] += a3 * b4.w;
        }
        #pragma unroll
        for (int i = 0; i < 4; i++) {
            float4 r4 = make_float4(acc[i][0], acc[i][1], acc[i][2], acc[i][3]);
            *reinterpret_cast<float4*>(Om[m] + (size_t)(row0 + ty * 4 + i) * 64 + tx * 4) = r4;
        }
    }
}

// ---------------- flash attention (fp32, 64x64 tiles, online softmax) --------
static constexpr int ATTN_SMEM_BYTES = (4 * 64 * 68 + 3 * 64) * 4;   // 70400 B

__global__ __launch_bounds__(256) void k_attn(
    const float* __restrict__ qg, const float* __restrict__ kg,
    const float* __restrict__ vg, float* __restrict__ og)
{
    extern __shared__ __align__(16) float sm[];
    float* qs  = sm;                 // [64][68]
    float* kst = sm + 64 * 68;       // transposed [d][key], [64][68]
    float* vs  = sm + 2 * 64 * 68;   // [key][e], [64][68]
    float* ps  = sm + 3 * 64 * 68;   // scores / probs [64][68]
    float* m_s = sm + 4 * 64 * 68;
    float* l_s = m_s + 64;
    float* a_s = l_s + 64;

    int tid = threadIdx.x;
    int tx = tid & 15, ty = tid >> 4;
    int s0 = blockIdx.x * 64;
    int bh = blockIdx.y;
    int b = bh >> 3, hh = bh & 7;
    const size_t base = (size_t)b * cS * cD + hh * 64;

    #pragma unroll
    for (int u = 0; u < 4; u++) {
        int f = tid + u * 256;
        int r = f >> 4, c4 = f & 15;
        float4 val = make_float4(0.f, 0.f, 0.f, 0.f);
        if (s0 + r < cS)
            val = *reinterpret_cast<const float4*>(qg + base + (size_t)(s0 + r) * cD + c4 * 4);
        *reinterpret_cast<float4*>(&qs[r * 68 + c4 * 4]) = val;
    }
    if (tid < 64) { m_s[tid] = -1e30f; l_s[tid] = 0.f; }

    float acc[4][4] = {};

    for (int kb = 0; kb < cS; kb += 64) {
        __syncthreads();
        #pragma unroll
        for (int u = 0; u < 4; u++) {
            int f = tid + u * 256;
            int r = f >> 4, c4 = f & 15;
            float4 kv = make_float4(0.f, 0.f, 0.f, 0.f);
            float4 vv = make_float4(0.f, 0.f, 0.f, 0.f);
            if (kb + r < cS) {
                kv = *reinterpret_cast<const float4*>(kg + base + (size_t)(kb + r) * cD + c4 * 4);
                vv = *reinterpret_cast<const float4*>(vg + base + (size_t)(kb + r) * cD + c4 * 4);
            }
            kst[(c4 * 4 + 0) * 68 + r] = kv.x;
            kst[(c4 * 4 + 1) * 68 + r] = kv.y;
            kst[(c4 * 4 + 2) * 68 + r] = kv.z;
            kst[(c4 * 4 + 3) * 68 + r] = kv.w;
            *reinterpret_cast<float4*>(&vs[r * 68 + c4 * 4]) = vv;
        }
        __syncthreads();

        // stage A: S = Q K^T
        float scv[4][4] = {};
        #pragma unroll
        for (int d = 0; d < 64; d++) {
            float a0 = qs[(ty * 4 + 0) * 68 + d];
            float a1 = qs[(ty * 4 + 1) * 68 + d];
            float a2 = qs[(ty * 4 + 2) * 68 + d];
            float a3 = qs[(ty * 4 + 3) * 68 + d];
            float4 b4 = *reinterpret_cast<const float4*>(&kst[d * 68 + tx * 4]);
            scv[0][0] += a0 * b4.x; scv[0][1] += a0 * b4.y; scv[0][2] += a0 * b4.z; scv[0][3] += a0 * b4.w;
            scv[1][0] += a1 * b4.x; scv[1][1] += a1 * b4.y; scv[1][2] += a1 * b4.z; scv[1][3] += a1 * b4.w;
            scv[2][0] += a2 * b4.x; scv[2][1] += a2 * b4.y; scv[2][2] += a2 * b4.z; scv[2][3] += a2 * b4.w;
            scv[3][0] += a3 * b4.x; scv[3][1] += a3 * b4.y; scv[3][2] += a3 * b4.z; scv[3][3] += a3 * b4.w;
        }
        #pragma unroll
        for (int i = 0; i < 4; i++) {
            int c = kb + tx * 4;
            float4 r4;
            r4.x = (c + 0 < cS) ? scv[i][0] * 0.125f : -1e30f;
            r4.y = (c + 1 < cS) ? scv[i][1] * 0.125f : -1e30f;
            r4.z = (c + 2 < cS) ? scv[i][2] * 0.125f : -1e30f;
            r4.w = (c + 3 < cS) ? scv[i][3] * 0.125f : -1e30f;
            *reinterpret_cast<float4*>(&ps[(ty * 4 + i) * 68 + tx * 4]) = r4;
        }
        __syncthreads();

        // stage B: online softmax (4 threads per row)
        {
            int row = tid >> 2, qt = tid & 3;
            float* pr = &ps[row * 68 + qt * 16];
            float lm = -1e30f;
            #pragma unroll
            for (int c = 0; c < 16; c++) lm = fmaxf(lm, pr[c]);
            lm = fmaxf(lm, __shfl_xor_sync(0xffffffffu, lm, 1));
            lm = fmaxf(lm, __shfl_xor_sync(0xffffffffu, lm, 2));
            float m_old = m_s[row];
            float m_new = fmaxf(m_old, lm);
            float alpha = __expf(m_old - m_new);
            float lsum = 0.f;
            #pragma unroll
            for (int c = 0; c < 16; c++) {
                float p = __expf(pr[c] - m_new);
                pr[c] = p;
                lsum += p;
            }
            lsum += __shfl_xor_sync(0xffffffffu, lsum, 1);
            lsum += __shfl_xor_sync(0xffffffffu, lsum, 2);
            if (qt == 0) {
                m_s[row] = m_new;
                l_s[row] = l_s[row] * alpha + lsum;
                a_s[row] = alpha;
            }
        }
        __syncthreads();

        // stage C: O = alpha*O + P V
        #pragma unroll
        for (int i = 0; i < 4; i++) {
            float al = a_s[ty * 4 + i];
            acc[i][0] *= al; acc[i][1] *= al; acc[i][2] *= al; acc[i][3] *= al;
        }
        #pragma unroll
        for (int c = 0; c < 64; c++) {
            float4 v4 = *reinterpret_cast<const float4*>(&vs[c * 68 + tx * 4]);
            float p0 = ps[(ty * 4 + 0) * 68 + c];
            float p1 = ps[(ty * 4 + 1) * 68 + c];
            float p2 = ps[(ty * 4 + 2) * 68 + c];
            float p3 = ps[(ty * 4 + 3) * 68 + c];
            acc[0][0] += p0 * v4.x; acc[0][1] += p0 * v4.y; acc[0][2] += p0 * v4.z; acc[0][3] += p0 * v4.w;
            acc[1][0] += p1 * v4.x; acc[1][1] += p1 * v4.y; acc[1][2] += p1 * v4.z; acc[1][3] += p1 * v4.w;
            acc[2][0] += p2 * v4.x; acc[2][1] += p2 * v4.y; acc[2][2] += p2 * v4.z; acc[2][3] += p2 * v4.w;
            acc[3][0] += p3 * v4.x; acc[3][1] += p3 * v4.y; acc[3][2] += p3 * v4.z; acc[3][3] += p3 * v4.w;
        }
    }

    #pragma unroll
    for (int i = 0; i < 4; i++) {
        int s = s0 + ty * 4 + i;
        if (s < cS) {
            float inv = 1.f / l_s[ty * 4 + i];
            float4 r4 = make_float4(acc[i][0] * inv, acc[i][1] * inv, acc[i][2] * inv, acc[i][3] * inv);
            *reinterpret_cast<float4*>(og + base + (size_t)s * cD + tx * 4) = r4;
        }
    }
}

// ---------------- generic SGEMM: C = A @ B^T + bias (+resid) (+relu) ---------
// A [M,K] rm, B [N,K] rm. M%128==0, N%128==0, K%16==0 (guaranteed by shapes).
template<bool RELU, bool RES>
__global__ __launch_bounds__(256) void k_sgemm(
    const float* __restrict__ A, const float* __restrict__ Bm,
    const float* __restrict__ bias, const float* __restrict__ resid,
    float* __restrict__ C, int M, int N, int K)
{
    constexpr int ST = 132;
    __shared__ __align__(16) float As[16][ST];
    __shared__ __align__(16) float Bs[16][ST];
    int tid = threadIdx.x;
    int tx = tid & 15, ty = tid >> 4;
    int m0 = blockIdx.y * 128;
    int n0 = blockIdx.x * 128;
    int r0 = tid >> 2;
    int c40 = tid & 3;

    float acc[8][8] = {};
    float4 pa[2], pb[2];

    auto gload = [&](const float* __restrict__ P, int base, int kt, float4* pr) {
        #pragma unroll
        for (int u = 0; u < 2; u++) {
            int r = r0 + u * 64;
            pr[u] = *reinterpret_cast<const float4*>(P + (size_t)(base + r) * K + kt * 16 + c40 * 4);
        }
    };
    auto sstore = [&](float* Sp, float4* pr) {
        #pragma unroll
        for (int u = 0; u < 2; u++) {
            int r = r0 + u * 64;
            Sp[(c40 * 4 + 0) * ST + r] = pr[u].x;
            Sp[(c40 * 4 + 1) * ST + r] = pr[u].y;
            Sp[(c40 * 4 + 2) * ST + r] = pr[u].z;
            Sp[(c40 * 4 + 3) * ST + r] = pr[u].w;
        }
    };

    int nk = K >> 4;
    gload(A,  m0, 0, pa);
    gload(Bm, n0, 0, pb);
    for (int kt = 0; kt < nk; kt++) {
        __syncthreads();
        sstore(&As[0][0], pa);
        sstore(&Bs[0][0], pb);
        __syncthreads();
        if (kt + 1 < nk) { gload(A, m0, kt + 1, pa); gload(Bm, n0, kt + 1, pb); }
        #pragma unroll
        for (int kk = 0; kk < 16; kk++) {
            float4 a0 = *reinterpret_cast<const float4*>(&As[kk][ty * 4]);
            float4 a1 = *reinterpret_cast<const float4*>(&As[kk][64 + ty * 4]);
            float4 b0 = *reinterpret_cast<const float4*>(&Bs[kk][tx * 4]);
            float4 b1 = *reinterpret_cast<const float4*>(&Bs[kk][64 + tx * 4]);
            float av[8] = {a0.x, a0.y, a0.z, a0.w, a1.x, a1.y, a1.z, a1.w};
            float bv[8] = {b0.x, b0.y, b0.z, b0.w, b1.x, b1.y, b1.z, b1.w};
            #pragma unroll
            for (int i = 0; i < 8; i++)
                #pragma unroll
                for (int j = 0; j < 8; j++)
                    acc[i][j] += av[i] * bv[j];
        }
    }

    #pragma unroll
    for (int i = 0; i < 8; i++) {
        int m = m0 + ((i < 4) ? (ty * 4 + i) : (64 + ty * 4 + i - 4));
        #pragma unroll
        for (int g = 0; g < 2; g++) {
            int n = n0 + ((g == 0) ? tx * 4 : 64 + tx * 4);
            float4 r4;
            r4.x = acc[i][g * 4 + 0] + bias[n + 0];
            r4.y = acc[i][g * 4 + 1] + bias[n + 1];
            r4.z = acc[i][g * 4 + 2] + bias[n + 2];
            r4.w = acc[i][g * 4 + 3] + bias[n + 3];
            if (RES) {
                float4 rr = *reinterpret_cast<const float4*>(resid + (size_t)m * N + n);
                r4.x += rr.x; r4.y += rr.y; r4.z += rr.z; r4.w += rr.w;
            }
            if (RELU) {
                r4.x = fmaxf(r4.x, 0.f); r4.y = fmaxf(r4.y, 0.f);
                r4.z = fmaxf(r4.z, 0.f); r4.w = fmaxf(r4.w, 0.f);
            }
            *reinterpret_cast<float4*>(C + (size_t)m * N + n) = r4;
        }
    }
}

// ---------------- LayerNorm over rows of 512 ----------------
__global__ void k_ln(const float* __restrict__ x, const float* __restrict__ w,
                     const float* __restrict__ bb, float* __restrict__ out)
{
    __shared__ float red[4];
    int row = blockIdx.x;
    int t = threadIdx.x;   // 128 threads, 4 floats each
    const float4 v = reinterpret_cast<const float4*>(x + (size_t)row * cD)[t];
    float s = v.x + v.y + v.z + v.w;
    #pragma unroll
    for (int o = 16; o > 0; o >>= 1) s += __shfl_xor_sync(0xffffffffu, s, o);
    if ((t & 31) == 0) red[t >> 5] = s;
    __syncthreads();
    float mean = (red[0] + red[1] + red[2] + red[3]) * (1.0f / cD);
    float dx = v.x - mean, dy = v.y - mean, dz = v.z - mean, dw = v.w - mean;
    float s2 = dx * dx + dy * dy + dz * dz + dw * dw;
    #pragma unroll
    for (int o = 16; o > 0; o >>= 1) s2 += __shfl_xor_sync(0xffffffffu, s2, o);
    __syncthreads();
    if ((t & 31) == 0) red[t >> 5] = s2;
    __syncthreads();
    float var = (red[0] + red[1] + red[2] + red[3]) * (1.0f / cD);
    float inv = rsqrtf(var + 1e-5f);
    float4 wv = reinterpret_cast<const float4*>(w)[t];
    float4 bv = reinterpret_cast<const float4*>(bb)[t];
    float4 r4;
    r4.x = dx * inv * wv.x + bv.x;
    r4.y = dy * inv * wv.y + bv.y;
    r4.z = dz * inv * wv.z + bv.z;
    r4.w = dw * inv * wv.w + bv.w;
    reinterpret_cast<float4*>(out + (size_t)row * cD)[t] = r4;
}

// ---------------- driver ----------------
extern "C" void kernel_launch(void* const* d_in, const int* in_sizes, int n_in,
                              void* d_out, int out_size)
{
    const int*   x    = (const int*)  d_in[0];
    const float* emb  = (const float*)d_in[1];
    const float* pe   = (const float*)d_in[2];
    const float* Wq   = (const float*)d_in[3];
    const float* Wk   = (const float*)d_in[4];
    const float* Wv   = (const float*)d_in[5];
    const float* Wo   = (const float*)d_in[6];
    const float* bo   = (const float*)d_in[7];
    const float* ln1w = (const float*)d_in[8];
    const float* ln1b = (const float*)d_in[9];
    const float* W1   = (const float*)d_in[10];
    const float* b1   = (const float*)d_in[11];
    const float* W2   = (const float*)d_in[12];
    const float* b2   = (const float*)d_in[13];
    const float* ln2w = (const float*)d_in[14];
    const float* ln2b = (const float*)d_in[15];
    float* out = (float*)d_out;

    float *h, *q, *k, *v, *o, *t, *n1, *t2, *f1;
    cudaGetSymbolAddress((void**)&h,  g_h);
    cudaGetSymbolAddress((void**)&q,  g_q);
    cudaGetSymbolAddress((void**)&k,  g_k);
    cudaGetSymbolAddress((void**)&v,  g_v);
    cudaGetSymbolAddress((void**)&o,  g_o);
    cudaGetSymbolAddress((void**)&t,  g_t);
    cudaGetSymbolAddress((void**)&n1, g_n1);
    cudaGetSymbolAddress((void**)&t2, g_t2);
    cudaGetSymbolAddress((void**)&f1, g_f1);

    cudaFuncSetAttribute(k_attn, cudaFuncAttributeMaxDynamicSharedMemorySize, ATTN_SMEM_BYTES);

    k_embed<<<(cBS * cD / 4 + 255) / 256, 256>>>(x, emb, pe, h);

    for (int l = 0; l < cL; l++) {
        k_qkv<<<cBSH / 64, 256>>>(h, Wq + l * cHD * cHD, Wk + l * cHD * cHD,
                                  Wv + l * cHD * cHD, q, k, v);
        k_attn<<<dim3((cS + 63) / 64, cB * cH), 256, ATTN_SMEM_BYTES>>>(q, k, v, o);
        // o @ Wo^T + bo + h -> t
        k_sgemm<false, true><<<dim3(cD / 128, cBS / 128), 256>>>(
            o, Wo + (size_t)l * cD * cD, bo + l * cD, h, t, cBS, cD, cD);
        k_ln<<<cBS, 128>>>(t, ln1w + l * cD, ln1b + l * cD, n1);
        // relu(n1 @ W1^T + b1) -> f1
        k_sgemm<true, false><<<dim3(cF / 128, cBS / 128), 256>>>(
            n1, W1 + (size_t)l * cF * cD, b1 + l * cF, nullptr, f1, cBS, cF, cD);
        // f1 @ W2^T + b2 + n1 -> t2
        k_sgemm<false, true><<<dim3(cD / 128, cBS / 128), 256>>>(
            f1, W2 + (size_t)l * cD * cF, b2 + l * cD, n1, t2, cBS, cD, cF);
        k_ln<<<cBS, 128>>>(t2, ln2w + l * cD, ln2b + l * cD, (l == cL - 1) ? out : h);
    }
}

// round 7
// speedup vs baseline: 1.5286x; 1.5286x over previous
#include <cuda_runtime.h>
#include <cuda_bf16.h>
#include <stdint.h>
#include <math.h>

// ---------------- problem constants ----------------
static constexpr int cB   = 32;
static constexpr int cS   = 744;
static constexpr int cD   = 512;
static constexpr int cH   = 8;
static constexpr int cHD  = 64;
static constexpr int cL   = 4;
static constexpr int cF   = 2048;           // EXP * D
static constexpr int cBS  = cB * cS;        // 23808 = 186 * 128
static constexpr int cBSH = cBS * cH;       // 190464

// ---------------- scratch (device globals; no allocations allowed) ----------
__device__ float g_h [cBS * cD];
__device__ float g_q [cBS * cD];
__device__ float g_k [cBS * cD];
__device__ float g_v [cBS * cD];
__device__ float g_o [cBS * cD];
__device__ float g_t [cBS * cD];
__device__ float g_n1[cBS * cD];
__device__ float g_t2[cBS * cD];
__device__ float g_f1[(size_t)cBS * cF];

// =====================================================================
// helpers
// =====================================================================
__device__ __forceinline__ uint32_t smem_u32(const void* p) {
    uint32_t a;
    asm("{ .reg .u64 t; cvta.to.shared.u64 t, %1; cvt.u32.u64 %0, t; }" : "=r"(a) : "l"(p));
    return a;
}
__device__ __forceinline__ void ldsm4(uint32_t* r, uint32_t a) {
    asm volatile("ldmatrix.sync.aligned.m8n8.x4.shared.b16 {%0,%1,%2,%3}, [%4];"
                 : "=r"(r[0]), "=r"(r[1]), "=r"(r[2]), "=r"(r[3]) : "r"(a));
}
__device__ __forceinline__ void mma16816(float* c, const uint32_t* a,
                                         uint32_t b0, uint32_t b1) {
    asm volatile(
        "mma.sync.aligned.m16n8k16.row.col.f32.bf16.bf16.f32 "
        "{%0,%1,%2,%3}, {%4,%5,%6,%7}, {%8,%9}, {%0,%1,%2,%3};"
        : "+f"(c[0]), "+f"(c[1]), "+f"(c[2]), "+f"(c[3])
        : "r"(a[0]), "r"(a[1]), "r"(a[2]), "r"(a[3]), "r"(b0), "r"(b1));
}
__device__ __forceinline__ uint32_t pack_bf2(__nv_bfloat16 x, __nv_bfloat16 y) {
    __nv_bfloat162 t(x, y);
    return *reinterpret_cast<uint32_t*>(&t);
}

// =====================================================================
// bf16x3-compensated tensor GEMM: C = A[M,K] @ B[N,K]^T + bias (+res)(+relu)
// Tile 128x128, K-block 32, 256 threads, warp grid 2(m) x 4(n).
// M%128==0, N%128==0, K%32==0.
// =====================================================================
static constexpr int SROW = 40;   // bf16 per smem row (32 data + 8 pad) = 80B

template<bool RELU, bool RES>
__global__ __launch_bounds__(256, 1) void mma_gemm(
    const float* __restrict__ A, const float* __restrict__ Bm,
    const float* __restrict__ bias, const float* __restrict__ resid,
    float* __restrict__ C, int M, int N, int K)
{
    __shared__ __align__(16) __nv_bfloat16 Ah[128 * SROW];
    __shared__ __align__(16) __nv_bfloat16 Al[128 * SROW];
    __shared__ __align__(16) __nv_bfloat16 Bh[128 * SROW];
    __shared__ __align__(16) __nv_bfloat16 Bl[128 * SROW];

    const int tid  = threadIdx.x;
    const int w    = tid >> 5, lane = tid & 31;
    const int m0   = blockIdx.y * 128, n0 = blockIdx.x * 128;
    const int wm   = (w & 1) * 64;       // warp m-offset within tile
    const int wn   = (w >> 1) * 32;      // warp n-offset within tile

    const uint32_t aAh = smem_u32(Ah), aAl = smem_u32(Al);
    const uint32_t aBh = smem_u32(Bh), aBl = smem_u32(Bl);

    // ldmatrix per-lane address components (bytes)
    // A: row = wm + mi*16 + (lane&15), col = kk*16 + (lane>>4)*8
    const uint32_t a_lane = (uint32_t)((wm + (lane & 15)) * SROW * 2 + (lane >> 4) * 16);
    // B: row = wn + j*16 + ((lane>>4)&1)*8 + (lane&7), col = kk*16 + ((lane>>3)&1)*8
    const uint32_t b_lane = (uint32_t)(
        (wn + ((lane >> 4) & 1) * 8 + (lane & 7)) * SROW * 2 + ((lane >> 3) & 1) * 16);

    float acc[4][4][4] = {};

    const int NK = K >> 5;

    // prefetch first K-block
    float4 pa[4], pb[4];
    #pragma unroll
    for (int u = 0; u < 4; u++) {
        int f = tid + u * 256;
        int rr = f >> 3, c4 = f & 7;
        pa[u] = *reinterpret_cast<const float4*>(A  + (size_t)(m0 + rr) * K + c4 * 4);
        pb[u] = *reinterpret_cast<const float4*>(Bm + (size_t)(n0 + rr) * K + c4 * 4);
    }

    for (int kt = 0; kt < NK; kt++) {
        __syncthreads();
        // convert fp32 -> bf16 hi + bf16 lo, store to smem
        #pragma unroll
        for (int u = 0; u < 4; u++) {
            int f = tid + u * 256;
            int rr = f >> 3, c4 = f & 7;
            int idx = rr * SROW + c4 * 4;
            {
                __nv_bfloat16 h0 = __float2bfloat16_rn(pa[u].x);
                __nv_bfloat16 h1 = __float2bfloat16_rn(pa[u].y);
                __nv_bfloat16 h2 = __float2bfloat16_rn(pa[u].z);
                __nv_bfloat16 h3 = __float2bfloat16_rn(pa[u].w);
                __nv_bfloat16 l0 = __float2bfloat16_rn(pa[u].x - __bfloat162float(h0));
                __nv_bfloat16 l1 = __float2bfloat16_rn(pa[u].y - __bfloat162float(h1));
                __nv_bfloat16 l2 = __float2bfloat16_rn(pa[u].z - __bfloat162float(h2));
                __nv_bfloat16 l3 = __float2bfloat16_rn(pa[u].w - __bfloat162float(h3));
                *reinterpret_cast<uint2*>(Ah + idx) = make_uint2(pack_bf2(h0, h1), pack_bf2(h2, h3));
                *reinterpret_cast<uint2*>(Al + idx) = make_uint2(pack_bf2(l0, l1), pack_bf2(l2, l3));
            }
            {
                __nv_bfloat16 h0 = __float2bfloat16_rn(pb[u].x);
                __nv_bfloat16 h1 = __float2bfloat16_rn(pb[u].y);
                __nv_bfloat16 h2 = __float2bfloat16_rn(pb[u].z);
                __nv_bfloat16 h3 = __float2bfloat16_rn(pb[u].w);
                __nv_bfloat16 l0 = __float2bfloat16_rn(pb[u].x - __bfloat162float(h0));
                __nv_bfloat16 l1 = __float2bfloat16_rn(pb[u].y - __bfloat162float(h1));
                __nv_bfloat16 l2 = __float2bfloat16_rn(pb[u].z - __bfloat162float(h2));
                __nv_bfloat16 l3 = __float2bfloat16_rn(pb[u].w - __bfloat162float(h3));
                *reinterpret_cast<uint2*>(Bh + idx) = make_uint2(pack_bf2(h0, h1), pack_bf2(h2, h3));
                *reinterpret_cast<uint2*>(Bl + idx) = make_uint2(pack_bf2(l0, l1), pack_bf2(l2, l3));
            }
        }
        __syncthreads();

        // prefetch next K-block (overlaps with MMA below)
        if (kt + 1 < NK) {
            #pragma unroll
            for (int u = 0; u < 4; u++) {
                int f = tid + u * 256;
                int rr = f >> 3, c4 = f & 7;
                pa[u] = *reinterpret_cast<const float4*>(
                    A  + (size_t)(m0 + rr) * K + (kt + 1) * 32 + c4 * 4);
                pb[u] = *reinterpret_cast<const float4*>(
                    Bm + (size_t)(n0 + rr) * K + (kt + 1) * 32 + c4 * 4);
            }
        }

        // MMA over the two k16 halves of this K-block
        #pragma unroll
        for (int kk = 0; kk < 2; kk++) {
            const uint32_t kof = (uint32_t)(kk * 32);   // 16 bf16 = 32 bytes
            uint32_t ah[4][4], al[4][4];
            #pragma unroll
            for (int mi = 0; mi < 4; mi++) {
                uint32_t off = a_lane + (uint32_t)(mi * 16 * SROW * 2) + kof;
                ldsm4(ah[mi], aAh + off);
                ldsm4(al[mi], aAl + off);
            }
            uint32_t bh[2][4], bl[2][4];
            #pragma unroll
            for (int j = 0; j < 2; j++) {
                uint32_t off = b_lane + (uint32_t)(j * 16 * SROW * 2) + kof;
                ldsm4(bh[j], aBh + off);
                ldsm4(bl[j], aBl + off);
            }
            #pragma unroll
            for (int mi = 0; mi < 4; mi++) {
                #pragma unroll
                for (int ni = 0; ni < 4; ni++) {
                    int j = ni >> 1, s = (ni & 1) * 2;
                    mma16816(acc[mi][ni], ah[mi], bh[j][s], bh[j][s + 1]);
                    mma16816(acc[mi][ni], ah[mi], bl[j][s], bl[j][s + 1]);
                    mma16816(acc[mi][ni], al[mi], bh[j][s], bh[j][s + 1]);
                }
            }
        }
    }

    // epilogue: fragment (mi,ni): rows t/4, t/4+8; cols (t%4)*2, +1
    const int rbase = m0 + wm + (lane >> 2);
    const int cgrp  = (lane & 3) * 2;
    #pragma unroll
    for (int mi = 0; mi < 4; mi++) {
        int r1 = rbase + mi * 16;
        int r2 = r1 + 8;
        #pragma unroll
        for (int ni = 0; ni < 4; ni++) {
            int col = n0 + wn + ni * 8 + cgrp;
            float2 bv = *reinterpret_cast<const float2*>(bias + col);
            float2 v1 = make_float2(acc[mi][ni][0] + bv.x, acc[mi][ni][1] + bv.y);
            float2 v2 = make_float2(acc[mi][ni][2] + bv.x, acc[mi][ni][3] + bv.y);
            if (RES) {
                float2 q1 = *reinterpret_cast<const float2*>(resid + (size_t)r1 * N + col);
                float2 q2 = *reinterpret_cast<const float2*>(resid + (size_t)r2 * N + col);
                v1.x += q1.x; v1.y += q1.y; v2.x += q2.x; v2.y += q2.y;
            }
            if (RELU) {
                v1.x = fmaxf(v1.x, 0.f); v1.y = fmaxf(v1.y, 0.f);
                v2.x = fmaxf(v2.x, 0.f); v2.y = fmaxf(v2.y, 0.f);
            }
            *reinterpret_cast<float2*>(C + (size_t)r1 * N + col) = v1;
            *reinterpret_cast<float2*>(C + (size_t)r2 * N + col) = v2;
        }
    }
}

// ---------------- embedding + positional encoding ----------------
__global__ void k_embed(const int* __restrict__ x, const float* __restrict__ emb,
                        const float* __restrict__ pe, float* __restrict__ h)
{
    int i = blockIdx.x * blockDim.x + threadIdx.x;
    const int n4 = cBS * cD / 4;
    if (i >= n4) return;
    int d4 = i & (cD / 4 - 1);
    int bs = i >> 7;
    int s  = bs % cS;
    int tok = x[bs];
    float4 e = reinterpret_cast<const float4*>(emb)[tok * (cD / 4) + d4];
    float4 p = reinterpret_cast<const float4*>(pe)[s * (cD / 4) + d4];
    const float sc = 22.62741699796952f;    // sqrt(512)
    float4 r;
    r.x = e.x * sc + p.x; r.y = e.y * sc + p.y;
    r.z = e.z * sc + p.z; r.w = e.w * sc + p.w;
    reinterpret_cast<float4*>(h)[i] = r;
}

// ---------------- fused QKV: [BSH,64] @ W^T for W in {Wq,Wk,Wv} --------------
__global__ __launch_bounds__(256) void k_qkv(
    const float* __restrict__ h,
    const float* __restrict__ Wq, const float* __restrict__ Wk, const float* __restrict__ Wv,
    float* __restrict__ q, float* __restrict__ k, float* __restrict__ v)
{
    __shared__ __align__(16) float xs[64][68];
    __shared__ __align__(16) float ws[64][64];
    int tid = threadIdx.x;
    int tx = tid & 15, ty = tid >> 4;
    int row0 = blockIdx.x * 64;

    #pragma unroll
    for (int u = 0; u < 4; u++) {
        int f = tid + u * 256;
        int r = f >> 4, c4 = f & 15;
        float4 val = reinterpret_cast<const float4*>(h + (size_t)(row0 + r) * 64)[c4];
        *reinterpret_cast<float4*>(&xs[r][c4 * 4]) = val;
    }

    const float* Wm[3] = {Wq, Wk, Wv};
    float*       Om[3] = {q,  k,  v };
    #pragma unroll
    for (int m = 0; m < 3; m++) {
        __syncthreads();
        #pragma unroll
        for (int u = 0; u < 4; u++) {
            int f = tid + u * 256;
            int e = f >> 4, c4 = f & 15;
            float4 w4 = reinterpret_cast<const float4*>(Wm[m] + e * 64)[c4];
            ws[c4 * 4 + 0][e] = w4.x;
            ws[c4 * 4 + 1][e] = w4.y;
            ws[c4 * 4 + 2][e] = w4.z;
            ws[c4 * 4 + 3][e] = w4.w;
        }
        __syncthreads();
        float acc[4][4] = {};
        #pragma unroll
        for (int d = 0; d < 64; d++) {
            float a0 = xs[ty * 4 + 0][d];
            float a1 = xs[ty * 4 + 1][d];
            float a2 = xs[ty * 4 + 2][d];
            float a3 = xs[ty * 4 + 3][d];
            float4 b4 = *reinterpret_cast<const float4*>(&ws[d][tx * 4]);
            acc[0][0] += a0 * b4.x; acc[0][1] += a0 * b4.y; acc[0][2] += a0 * b4.z; acc[0][3] += a0 * b4.w;
            acc[1][0] += a1 * b4.x; acc[1][1] += a1 * b4.y; acc[1][2] += a1 * b4.z; acc[1][3] += a1 * b4.w;
            acc[2][0] += a2 * b4.x; acc[2][1] += a2 * b4.y; acc[2][2] += a2 * b4.z; acc[2][3] += a2 * b4.w;
            acc[3][0] += a3 * b4.x; acc[3][1] += a3 * b4.y; acc[3][2] += a3 * b4.z; acc[3][3] += a3 * b4.w;
        }
        #pragma unroll
        for (int i = 0; i < 4; i++) {
            float4 r4 = make_float4(acc[i][0], acc[i][1], acc[i][2], acc[i][3]);
            *reinterpret_cast<float4*>(Om[m] + (size_t)(row0 + ty * 4 + i) * 64 + tx * 4) = r4;
        }
    }
}

// ---------------- flash attention (fp32, 64x64 tiles, online softmax) --------
static constexpr int ATTN_SMEM_BYTES = (4 * 64 * 68 + 3 * 64) * 4;   // 70400 B

__global__ __launch_bounds__(256) void k_attn(
    const float* __restrict__ qg, const float* __restrict__ kg,
    const float* __restrict__ vg, float* __restrict__ og)
{
    extern __shared__ __align__(16) float sm[];
    float* qs  = sm;
    float* kst = sm + 64 * 68;
    float* vs  = sm + 2 * 64 * 68;
    float* ps  = sm + 3 * 64 * 68;
    float* m_s = sm + 4 * 64 * 68;
    float* l_s = m_s + 64;
    float* a_s = l_s + 64;

    int tid = threadIdx.x;
    int tx = tid & 15, ty = tid >> 4;
    int s0 = blockIdx.x * 64;
    int bh = blockIdx.y;
    int b = bh >> 3, hh = bh & 7;
    const size_t base = (size_t)b * cS * cD + hh * 64;

    #pragma unroll
    for (int u = 0; u < 4; u++) {
        int f = tid + u * 256;
        int r = f >> 4, c4 = f & 15;
        float4 val = make_float4(0.f, 0.f, 0.f, 0.f);
        if (s0 + r < cS)
            val = *reinterpret_cast<const float4*>(qg + base + (size_t)(s0 + r) * cD + c4 * 4);
        *reinterpret_cast<float4*>(&qs[r * 68 + c4 * 4]) = val;
    }
    if (tid < 64) { m_s[tid] = -1e30f; l_s[tid] = 0.f; }

    float acc[4][4] = {};

    for (int kb = 0; kb < cS; kb += 64) {
        __syncthreads();
        #pragma unroll
        for (int u = 0; u < 4; u++) {
            int f = tid + u * 256;
            int r = f >> 4, c4 = f & 15;
            float4 kv = make_float4(0.f, 0.f, 0.f, 0.f);
            float4 vv = make_float4(0.f, 0.f, 0.f, 0.f);
            if (kb + r < cS) {
                kv = *reinterpret_cast<const float4*>(kg + base + (size_t)(kb + r) * cD + c4 * 4);
                vv = *reinterpret_cast<const float4*>(vg + base + (size_t)(kb + r) * cD + c4 * 4);
            }
            kst[(c4 * 4 + 0) * 68 + r] = kv.x;
            kst[(c4 * 4 + 1) * 68 + r] = kv.y;
            kst[(c4 * 4 + 2) * 68 + r] = kv.z;
            kst[(c4 * 4 + 3) * 68 + r] = kv.w;
            *reinterpret_cast<float4*>(&vs[r * 68 + c4 * 4]) = vv;
        }
        __syncthreads();

        float scv[4][4] = {};
        #pragma unroll
        for (int d = 0; d < 64; d++) {
            float a0 = qs[(ty * 4 + 0) * 68 + d];
            float a1 = qs[(ty * 4 + 1) * 68 + d];
            float a2 = qs[(ty * 4 + 2) * 68 + d];
            float a3 = qs[(ty * 4 + 3) * 68 + d];
            float4 b4 = *reinterpret_cast<const float4*>(&kst[d * 68 + tx * 4]);
            scv[0][0] += a0 * b4.x; scv[0][1] += a0 * b4.y; scv[0][2] += a0 * b4.z; scv[0][3] += a0 * b4.w;
            scv[1][0] += a1 * b4.x; scv[1][1] += a1 * b4.y; scv[1][2] += a1 * b4.z; scv[1][3] += a1 * b4.w;
            scv[2][0] += a2 * b4.x; scv[2][1] += a2 * b4.y; scv[2][2] += a2 * b4.z; scv[2][3] += a2 * b4.w;
            scv[3][0] += a3 * b4.x; scv[3][1] += a3 * b4.y; scv[3][2] += a3 * b4.z; scv[3][3] += a3 * b4.w;
        }
        #pragma unroll
        for (int i = 0; i < 4; i++) {
            int c = kb + tx * 4;
            float4 r4;
            r4.x = (c + 0 < cS) ? scv[i][0] * 0.125f : -1e30f;
            r4.y = (c + 1 < cS) ? scv[i][1] * 0.125f : -1e30f;
            r4.z = (c + 2 < cS) ? scv[i][2] * 0.125f : -1e30f;
            r4.w = (c + 3 < cS) ? scv[i][3] * 0.125f : -1e30f;
            *reinterpret_cast<float4*>(&ps[(ty * 4 + i) * 68 + tx * 4]) = r4;
        }
        __syncthreads();

        {
            int row = tid >> 2, qt = tid & 3;
            float* pr = &ps[row * 68 + qt * 16];
            float lm = -1e30f;
            #pragma unroll
            for (int c = 0; c < 16; c++) lm = fmaxf(lm, pr[c]);
            lm = fmaxf(lm, __shfl_xor_sync(0xffffffffu, lm, 1));
            lm = fmaxf(lm, __shfl_xor_sync(0xffffffffu, lm, 2));
            float m_old = m_s[row];
            float m_new = fmaxf(m_old, lm);
            float alpha = __expf(m_old - m_new);
            float lsum = 0.f;
            #pragma unroll
            for (int c = 0; c < 16; c++) {
                float p = __expf(pr[c] - m_new);
                pr[c] = p;
                lsum += p;
            }
            lsum += __shfl_xor_sync(0xffffffffu, lsum, 1);
            lsum += __shfl_xor_sync(0xffffffffu, lsum, 2);
            if (qt == 0) {
                m_s[row] = m_new;
                l_s[row] = l_s[row] * alpha + lsum;
                a_s[row] = alpha;
            }
        }
        __syncthreads();

        #pragma unroll
        for (int i = 0; i < 4; i++) {
            float al = a_s[ty * 4 + i];
            acc[i][0] *= al; acc[i][1] *= al; acc[i][2] *= al; acc[i][3] *= al;
        }
        #pragma unroll
        for (int c = 0; c < 64; c++) {
            float4 v4 = *reinterpret_cast<const float4*>(&vs[c * 68 + tx * 4]);
            float p0 = ps[(ty * 4 + 0) * 68 + c];
            float p1 = ps[(ty * 4 + 1) * 68 + c];
            float p2 = ps[(ty * 4 + 2) * 68 + c];
            float p3 = ps[(ty * 4 + 3) * 68 + c];
            acc[0][0] += p0 * v4.x; acc[0][1] += p0 * v4.y; acc[0][2] += p0 * v4.z; acc[0][3] += p0 * v4.w;
            acc[1][0] += p1 * v4.x; acc[1][1] += p1 * v4.y; acc[1][2] += p1 * v4.z; acc[1][3] += p1 * v4.w;
            acc[2][0] += p2 * v4.x; acc[2][1] += p2 * v4.y; acc[2][2] += p2 * v4.z; acc[2][3] += p2 * v4.w;
            acc[3][0] += p3 * v4.x; acc[3][1] += p3 * v4.y; acc[3][2] += p3 * v4.z; acc[3][3] += p3 * v4.w;
        }
    }

    #pragma unroll
    for (int i = 0; i < 4; i++) {
        int s = s0 + ty * 4 + i;
        if (s < cS) {
            float inv = 1.f / l_s[ty * 4 + i];
            float4 r4 = make_float4(acc[i][0] * inv, acc[i][1] * inv, acc[i][2] * inv, acc[i][3] * inv);
            *reinterpret_cast<float4*>(og + base + (size_t)s * cD + tx * 4) = r4;
        }
    }
}

// ---------------- LayerNorm over rows of 512 ----------------
__global__ void k_ln(const float* __restrict__ x, const float* __restrict__ w,
                     const float* __restrict__ bb, float* __restrict__ out)
{
    __shared__ float red[4];
    int row = blockIdx.x;
    int t = threadIdx.x;
    const float4 v = reinterpret_cast<const float4*>(x + (size_t)row * cD)[t];
    float s = v.x + v.y + v.z + v.w;
    #pragma unroll
    for (int o = 16; o > 0; o >>= 1) s += __shfl_xor_sync(0xffffffffu, s, o);
    if ((t & 31) == 0) red[t >> 5] = s;
    __syncthreads();
    float mean = (red[0] + red[1] + red[2] + red[3]) * (1.0f / cD);
    float dx = v.x - mean, dy = v.y - mean, dz = v.z - mean, dw = v.w - mean;
    float s2 = dx * dx + dy * dy + dz * dz + dw * dw;
    #pragma unroll
    for (int o = 16; o > 0; o >>= 1) s2 += __shfl_xor_sync(0xffffffffu, s2, o);
    __syncthreads();
    if ((t & 31) == 0) red[t >> 5] = s2;
    __syncthreads();
    float var = (red[0] + red[1] + red[2] + red[3]) * (1.0f / cD);
    float inv = rsqrtf(var + 1e-5f);
    float4 wv = reinterpret_cast<const float4*>(w)[t];
    float4 bv = reinterpret_cast<const float4*>(bb)[t];
    float4 r4;
    r4.x = dx * inv * wv.x + bv.x;
    r4.y = dy * inv * wv.y + bv.y;
    r4.z = dz * inv * wv.z + bv.z;
    r4.w = dw * inv * wv.w + bv.w;
    reinterpret_cast<float4*>(out + (size_t)row * cD)[t] = r4;
}

// ---------------- driver ----------------
extern "C" void kernel_launch(void* const* d_in, const int* in_sizes, int n_in,
                              void* d_out, int out_size)
{
    const int*   x    = (const int*)  d_in[0];
    const float* emb  = (const float*)d_in[1];
    const float* pe   = (const float*)d_in[2];
    const float* Wq   = (const float*)d_in[3];
    const float* Wk   = (const float*)d_in[4];
    const float* Wv   = (const float*)d_in[5];
    const float* Wo   = (const float*)d_in[6];
    const float* bo   = (const float*)d_in[7];
    const float* ln1w = (const float*)d_in[8];
    const float* ln1b = (const float*)d_in[9];
    const float* W1   = (const float*)d_in[10];
    const float* b1   = (const float*)d_in[11];
    const float* W2   = (const float*)d_in[12];
    const float* b2   = (const float*)d_in[13];
    const float* ln2w = (const float*)d_in[14];
    const float* ln2b = (const float*)d_in[15];
    float* out = (float*)d_out;

    float *h, *q, *k, *v, *o, *t, *n1, *t2, *f1;
    cudaGetSymbolAddress((void**)&h,  g_h);
    cudaGetSymbolAddress((void**)&q,  g_q);
    cudaGetSymbolAddress((void**)&k,  g_k);
    cudaGetSymbolAddress((void**)&v,  g_v);
    cudaGetSymbolAddress((void**)&o,  g_o);
    cudaGetSymbolAddress((void**)&t,  g_t);
    cudaGetSymbolAddress((void**)&n1, g_n1);
    cudaGetSymbolAddress((void**)&t2, g_t2);
    cudaGetSymbolAddress((void**)&f1, g_f1);

    cudaFuncSetAttribute(k_attn, cudaFuncAttributeMaxDynamicSharedMemorySize, ATTN_SMEM_BYTES);

    k_embed<<<(cBS * cD / 4 + 255) / 256, 256>>>(x, emb, pe, h);

    for (int l = 0; l < cL; l++) {
        k_qkv<<<cBSH / 64, 256>>>(h, Wq + l * cHD * cHD, Wk + l * cHD * cHD,
                                  Wv + l * cHD * cHD, q, k, v);
        k_attn<<<dim3((cS + 63) / 64, cB * cH), 256, ATTN_SMEM_BYTES>>>(q, k, v, o);
        // o @ Wo^T + bo + h -> t
        mma_gemm<false, true><<<dim3(cD / 128, cBS / 128), 256>>>(
            o, Wo + (size_t)l * cD * cD, bo + l * cD, h, t, cBS, cD, cD);
        k_ln<<<cBS, 128>>>(t, ln1w + l * cD, ln1b + l * cD, n1);
        // relu(n1 @ W1^T + b1) -> f1
        mma_gemm<true, false><<<dim3(cF / 128, cBS / 128), 256>>>(
            n1, W1 + (size_t)l * cF * cD, b1 + l * cF, nullptr, f1, cBS, cF, cD);
        // f1 @ W2^T + b2 + n1 -> t2
        mma_gemm<false, true><<<dim3(cD / 128, cBS / 128), 256>>>(
            f1, W2 + (size_t)l * cD * cF, b2 + l * cD, n1, t2, cBS, cD, cF);
        k_ln<<<cBS, 128>>>(t2, ln2w + l * cD, ln2b + l * cD, (l == cL - 1) ? out : h);
    }
}